// round 3
// baseline (speedup 1.0000x reference)
#include <cuda_runtime.h>
#include <cuda_bf16.h>

// Problem: DotProductAttention_83476984365340
// softmax over singleton axis == 1.0 -> output = values.sum(axis=1).
// Pure HBM-bound column sum of values [32, 4096, 1024] f32 (512 MiB read).
//
// R1 (512 CTAs, plain loads):  82.37us ncu, DRAM 82.9%, 6565 GB/s  <- best
// R2 (1024 CTAs, __ldcs):      84.64us ncu, DRAM 80.5%             <- regression
// Conclusion: HBM stream-bandwidth bound; occupancy/MLP beyond R1 adds nothing.
// R3: revert to 512 CTAs / 1MiB-contiguous streams, keep explicit 8-wide
//     front-batched cached loads, dual accumulator chains.

#define B_DIM 32
#define T_DIM 4096
#define D_DIM 1024
#define T_CHUNKS 16
#define T_PER_CHUNK (T_DIM / T_CHUNKS)   // 256
#define THREADS 256                       // 256 threads * float4 = 1024 = D
#define BATCH 8                           // independent loads in flight per iter

__global__ __launch_bounds__(THREADS, 8)
void values_colsum_kernel(const float* __restrict__ values, float* __restrict__ out)
{
    const int b     = blockIdx.y;            // 0..31
    const int chunk = blockIdx.x;            // 0..15
    const int d4    = threadIdx.x;           // float4 index within row (0..255)

    const float4* __restrict__ p =
        reinterpret_cast<const float4*>(values) +
        (size_t)b * T_DIM * (D_DIM / 4) +
        (size_t)chunk * T_PER_CHUNK * (D_DIM / 4) +
        d4;

    float4 acc0 = make_float4(0.f, 0.f, 0.f, 0.f);
    float4 acc1 = make_float4(0.f, 0.f, 0.f, 0.f);

    #pragma unroll 2
    for (int it = 0; it < T_PER_CHUNK / BATCH; ++it) {
        // Front-batch BATCH independent 128-bit loads (default caching).
        float4 v[BATCH];
        #pragma unroll
        for (int k = 0; k < BATCH; ++k)
            v[k] = p[(size_t)k * (D_DIM / 4)];
        p += (size_t)BATCH * (D_DIM / 4);

        // Two independent accumulator chains.
        #pragma unroll
        for (int k = 0; k < BATCH; k += 2) {
            acc0.x += v[k].x;   acc0.y += v[k].y;
            acc0.z += v[k].z;   acc0.w += v[k].w;
            acc1.x += v[k+1].x; acc1.y += v[k+1].y;
            acc1.z += v[k+1].z; acc1.w += v[k+1].w;
        }
    }

    acc0.x += acc1.x; acc0.y += acc1.y; acc0.z += acc1.z; acc0.w += acc1.w;

    float* o = out + (size_t)b * D_DIM + d4 * 4;
    atomicAdd(o + 0, acc0.x);
    atomicAdd(o + 1, acc0.y);
    atomicAdd(o + 2, acc0.z);
    atomicAdd(o + 3, acc0.w);
}

extern "C" void kernel_launch(void* const* d_in, const int* in_sizes, int n_in,
                              void* d_out, int out_size)
{
    // Input order per reference setup_inputs(): query, keys, values, W
    const float* values = (const float*)d_in[2];
    float* out = (float*)d_out;

    cudaMemsetAsync(out, 0, (size_t)out_size * sizeof(float));

    dim3 grid(T_CHUNKS, B_DIM);
    values_colsum_kernel<<<grid, THREADS>>>(values, out);
}